// round 16
// speedup vs baseline: 5.5767x; 1.0076x over previous
#include <cuda_runtime.h>
#include <cuda_bf16.h>
#include <cuda_fp16.h>
#include <math.h>
#include <stdint.h>

#define BB 2
#define LL 2048
#define HH 2048
#define MM (BB*LL)
#define NC 16

// fp32 scratch
__device__ float g_lin [BB*LL*1024];
__device__ float g_bqkv[4096];
__device__ float g_po  [2*16*16*8192];
__device__ float g_pml [2*16*16*128];
// fp16 scratch
__device__ __half g_hsh [MM*HH];
__device__ __half g_xh  [MM*HH];
__device__ __half g_qkvh[MM*4096];
__device__ __half g_wqkv[4096*2048];
__device__ __half g_woh [2048*2048];
__device__ __half g_qh  [BB*8*LL*128];
__device__ __half g_kh  [BB*4*LL*128];
__device__ __half g_kl  [BB*4*LL*128];
__device__ __half g_qlin[BB*8*LL*128];
__device__ __half g_klin[BB*4*LL*128];
__device__ __half g_A   [BB*8*NC*16384];
__device__ __half g_P   [BB*8*NC*16384];

// ---------------- mma.sync helpers ----------------
__device__ __forceinline__ uint32_t s2u(const void* p) {
    return (uint32_t)__cvta_generic_to_shared(p);
}
__device__ __forceinline__ void ldm_x4(uint32_t* r, uint32_t addr) {
    asm volatile("ldmatrix.sync.aligned.m8n8.x4.shared.b16 {%0,%1,%2,%3}, [%4];"
                 : "=r"(r[0]), "=r"(r[1]), "=r"(r[2]), "=r"(r[3]) : "r"(addr));
}
__device__ __forceinline__ void ldm_x4t(uint32_t* r, uint32_t addr) {
    asm volatile("ldmatrix.sync.aligned.m8n8.x4.trans.shared.b16 {%0,%1,%2,%3}, [%4];"
                 : "=r"(r[0]), "=r"(r[1]), "=r"(r[2]), "=r"(r[3]) : "r"(addr));
}
__device__ __forceinline__ void mma_f16(float* c, const uint32_t* a, const uint32_t* b) {
    asm volatile("mma.sync.aligned.m16n8k16.row.col.f32.f16.f16.f32 "
                 "{%0,%1,%2,%3}, {%4,%5,%6,%7}, {%8,%9}, {%0,%1,%2,%3};"
                 : "+f"(c[0]), "+f"(c[1]), "+f"(c[2]), "+f"(c[3])
                 : "r"(a[0]), "r"(a[1]), "r"(a[2]), "r"(a[3]), "r"(b[0]), "r"(b[1]));
}
__device__ __forceinline__ void cp16(uint32_t dst, const void* src) {
    asm volatile("cp.async.cg.shared.global [%0], [%1], 16;"
                 :: "r"(dst), "l"(__cvta_generic_to_global(src)));
}
#define CP_COMMIT() asm volatile("cp.async.commit_group;" ::: "memory")
#define CP_WAIT1()  asm volatile("cp.async.wait_group 1;" ::: "memory")
#define CP_WAIT0()  asm volatile("cp.async.wait_group 0;" ::: "memory")
__device__ __forceinline__ float ex2(float x) {
    float y; asm("ex2.approx.ftz.f32 %0, %1;" : "=f"(y) : "f"(x)); return y;
}
#define LOG2E 1.4426950408889634f

// ---------------- convert kernels ----------------
__global__ void convert_h(const float* __restrict__ in, __half* __restrict__ hi)
{
    int i = (blockIdx.x*256 + threadIdx.x)*4;
    float4 v = *(const float4*)(in + i);
    __half h[4] = {__float2half_rn(v.x), __float2half_rn(v.y),
                   __float2half_rn(v.z), __float2half_rn(v.w)};
    *(uint2*)(hi + i) = *(uint2*)h;
}

__global__ void transpose_h(const float* __restrict__ W, __half* __restrict__ Th,
                            int Kd, int N)
{
    __shared__ float t[32][33];
    int n0 = blockIdx.x*32, k0 = blockIdx.y*32;
    int tx = threadIdx.x, ty = threadIdx.y;
#pragma unroll
    for (int i = 0; i < 4; i++)
        t[ty + 8*i][tx] = W[(size_t)(k0 + ty + 8*i)*N + n0 + tx];
    __syncthreads();
#pragma unroll
    for (int i = 0; i < 4; i++) {
        float v = t[tx][ty + 8*i];
        Th[(size_t)(n0 + ty + 8*i)*Kd + k0 + tx] = __float2half_rn(v);
    }
}

// ---------------- fp16 HMMA GEMM, templated output type ----------------
#define AOFF   0
#define BOFF   10240
extern __shared__ __align__(16) __half gsm2[];
template<bool HOUT>
__global__ __launch_bounds__(256, 1)
void gemm_mma(const __half* __restrict__ Ah, const __half* __restrict__ Bh,
              const float* __restrict__ bias, void* __restrict__ Cv, int N, int Kd)
{
    const int STG = 30720;
    const int tid = threadIdx.x, lane = tid & 31, wid = tid >> 5;
    const int n0 = blockIdx.x*256, m0 = blockIdx.y*128;
    const int wrow = (wid >> 2)*64, wcol = (wid & 3)*64;
    const uint32_t su = s2u(gsm2);

    float acc[4][8][4];
#pragma unroll
    for (int i = 0; i < 4; i++)
#pragma unroll
        for (int j = 0; j < 8; j++)
#pragma unroll
            for (int r = 0; r < 4; r++) acc[i][j][r] = 0.f;

    const int nch = Kd >> 5;

    auto load_stage = [&](int ci, int st) {
        const int k0 = ci << 5;
        const uint32_t sb = su + st*STG;
#pragma unroll
        for (int p = 0; p < 6; p++) {
            int idx = tid + p*256;
            int r = idx >> 2, seg = idx & 3;
            uint32_t doff; const __half* src;
            if (r < 128) { doff = AOFF + r*80 + seg*16;            src = Ah + (size_t)(m0 + r)*Kd + k0 + seg*8; }
            else         { int rb = r - 128; doff = BOFF + rb*80 + seg*16; src = Bh + (size_t)(n0 + rb)*Kd + k0 + seg*8; }
            cp16(sb + doff, src);
        }
    };

    load_stage(0, 0); CP_COMMIT();
    if (nch > 1) { load_stage(1, 1); CP_COMMIT(); }

    for (int i = 0; i < nch; i++) {
        if (i + 1 < nch) CP_WAIT1(); else CP_WAIT0();
        __syncthreads();
        if (i + 2 < nch) { load_stage(i + 2, (i + 2) % 3); CP_COMMIT(); }

        const uint32_t sA = su + (i % 3)*STG;
        const uint32_t sB = sA + BOFF;
        const int arow = wrow + (lane & 15);
        const int acol = (lane >> 4)*8;
        const int brow2 = wcol + ((lane >> 4) & 1)*8 + (lane & 7);
        const int bcol  = ((lane >> 3) & 1)*8;

#pragma unroll
        for (int ks = 0; ks < 2; ks++) {
            uint32_t ah[4][4], bh[8][2];
#pragma unroll
            for (int f = 0; f < 4; f++) {
                uint32_t off = (uint32_t)(((arow + 16*f)*40 + acol + ks*16)*2);
                ldm_x4(ah[f], sA + off);
            }
#pragma unroll
            for (int f2 = 0; f2 < 4; f2++) {
                uint32_t tmp[4];
                uint32_t off = (uint32_t)(((brow2 + 16*f2)*40 + bcol + ks*16)*2);
                ldm_x4(tmp, sB + off);
                bh[2*f2][0]   = tmp[0]; bh[2*f2][1]   = tmp[1];
                bh[2*f2+1][0] = tmp[2]; bh[2*f2+1][1] = tmp[3];
            }
#pragma unroll
            for (int fi = 0; fi < 4; fi++)
#pragma unroll
                for (int fj = 0; fj < 8; fj++)
                    mma_f16(acc[fi][fj], ah[fi], bh[fj]);
        }
    }

    const int g = lane >> 2, c = lane & 3;
#pragma unroll
    for (int fi = 0; fi < 4; fi++)
#pragma unroll
        for (int fj = 0; fj < 8; fj++) {
            int rr = m0 + wrow + 16*fi + g;
            int cc = n0 + wcol + 8*fj + 2*c;
            float b0 = bias ? bias[cc] : 0.f;
            float b1 = bias ? bias[cc + 1] : 0.f;
            float o00 = acc[fi][fj][0] + b0, o01 = acc[fi][fj][1] + b1;
            float o10 = acc[fi][fj][2] + b0, o11 = acc[fi][fj][3] + b1;
            if (HOUT) {
                __half* C = (__half*)Cv;
                *(__half2*)(C + (size_t)rr*N + cc)       = __floats2half2_rn(o00, o01);
                *(__half2*)(C + (size_t)(rr + 8)*N + cc) = __floats2half2_rn(o10, o11);
            } else {
                float* C = (float*)Cv;
                float2 v0 = {o00, o01}, v1 = {o10, o11};
                *(float2*)(C + (size_t)rr*N + cc) = v0;
                *(float2*)(C + (size_t)(rr + 8)*N + cc) = v1;
            }
        }
}

// ---------- rotary ----------
__global__ void rotary_kernel(const __half* __restrict__ qkv,
                              const int* __restrict__ pos, __half* __restrict__ qh,
                              __half* __restrict__ kh, __half* __restrict__ kl)
{
    const int l = blockIdx.x, b = blockIdx.y, d = threadIdx.x;
    const float p = (float)pos[l];
    const int dm = d & 63;
    const float ang = p * powf(1.0e6f, -((float)(2*dm))/128.0f);
    const float cs = cosf(ang), sn = sinf(ang);
    const float qscale = 0.08838834764831845f * LOG2E;
    const __half* row = qkv + (size_t)(b*LL + l)*4096;
#pragma unroll
    for (int h = 0; h < 8; h++) {
        float x  = __half2float(row[h*128 + d]);
        float xr = (d < 64) ? -__half2float(row[h*128 + d + 64])
                            :  __half2float(row[h*128 + d - 64]);
        qh[((size_t)(b*8 + h)*LL + l)*128 + d] = __float2half_rn((x*cs + xr*sn)*qscale);
    }
#pragma unroll
    for (int khh = 0; khh < 4; khh++) {
        float x  = __half2float(row[2048 + khh*128 + d]);
        float xr = (d < 64) ? -__half2float(row[2048 + khh*128 + d + 64])
                            :  __half2float(row[2048 + khh*128 + d - 64]);
        float rv = x*cs + xr*sn;
        __half h = __float2half_rn(rv);
        __half lo = __float2half_rn(rv - __half2float(h));
        size_t o = ((size_t)(b*4 + khh)*LL + l)*128 + d;
        kh[o] = h; kl[o] = lo;
    }
}

// ---------- causal depthwise conv(K=4) + SiLU -> fp16 outputs ----------
__global__ void conv_silu_kernel(const __half* __restrict__ qkv,
                                 const float* __restrict__ qcw, const float* __restrict__ qcb,
                                 const float* __restrict__ kcw, const float* __restrict__ kcb,
                                 __half* __restrict__ qlin, __half* __restrict__ klin)
{
    const int l = blockIdx.x, b = blockIdx.y, tid = threadIdx.x;
    for (int c = tid; c < 1024; c += 256) {
        float y = qcb[c];
#pragma unroll
        for (int i = 0; i < 4; i++) {
            int lp = l - 3 + i;
            if (lp >= 0) y += __half2float(qkv[(size_t)(b*LL + lp)*4096 + 1024 + c]) * qcw[c*4 + i];
        }
        y = y / (1.0f + expf(-y));
        qlin[((size_t)(b*8 + (c >> 7))*LL + l)*128 + (c & 127)] = __float2half_rn(y);
    }
    for (int c = 512 + tid; c < 1024; c += 256) {
        float y = kcb[c];
#pragma unroll
        for (int i = 0; i < 4; i++) {
            int lp = l - 3 + i;
            if (lp >= 0) y += __half2float(qkv[(size_t)(b*LL + lp)*4096 + 2048 + c]) * kcw[c*4 + i];
        }
        y = y / (1.0f + expf(-y));
        klin[((size_t)(b*4 + ((c - 512) >> 7))*LL + l)*128 + (c & 127)] = __float2half_rn(y);
    }
}

// ---------- flash attention, split-KV, V single fp16 ----------
#define QS 136
extern __shared__ __align__(16) __half fsmh[];
__global__ __launch_bounds__(128)
void flash_mma(const __half* __restrict__ qh, const __half* __restrict__ kh,
               const __half* __restrict__ kl, const __half* __restrict__ qkv,
               float* __restrict__ po, float* __restrict__ pml, __half* __restrict__ X)
{
    const int qt = 31 - (int)blockIdx.y;
    const int split = blockIdx.x;
    if (split == 1 && qt < 16) return;
    const int bh = blockIdx.z;
    const int b = bh >> 3, h = bh & 7;

    __half* sQ  = fsmh;
    __half* sKh = sQ  + 64*QS;
    __half* sKl = sKh + 64*QS;
    __half* sV  = sKl + 64*QS;

    const int tid = threadIdx.x, lane = tid & 31, wid = tid >> 5;
    const int kvh = h >> 1;
    const int wr = wid*16;

    {
        const __half* Qb = qh + ((size_t)(b*8 + h)*LL + qt*64)*128;
#pragma unroll
        for (int t = 0; t < 8; t++) {
            int idx = tid + t*128;
            int r = idx >> 4, u = idx & 15;
            *(uint4*)&sQ[r*QS + u*8] = *(const uint4*)(Qb + r*128 + u*8);
        }
    }

    float m0 = -INFINITY, m1 = -INFINITY, ls0 = 0.f, ls1 = 0.f;
    float oacc[16][4];
#pragma unroll
    for (int n = 0; n < 16; n++)
#pragma unroll
        for (int r = 0; r < 4; r++) oacc[n][r] = 0.f;

    const __half* Khb0 = kh + (size_t)(b*4 + kvh)*LL*128;
    const __half* Klb0 = kl + (size_t)(b*4 + kvh)*LL*128;
    const __half* Vb0  = qkv + (size_t)(b*LL)*4096 + 3072 + kvh*128;

    const int kt0 = split*16;
    const int ktend = (qt < kt0 + 15) ? qt : (kt0 + 15);

    for (int kt = kt0; kt <= ktend; kt++) {
        __syncthreads();
        {
            const __half* Khb = Khb0 + (size_t)(kt*64)*128;
            const __half* Klb = Klb0 + (size_t)(kt*64)*128;
            const __half* Vb  = Vb0  + (size_t)(kt*64)*4096;
#pragma unroll
            for (int t = 0; t < 8; t++) {
                int idx = tid + t*128;
                int r = idx >> 4, u = idx & 15;
                uint32_t so = (uint32_t)(r*QS + u*8);
                *(uint4*)&sKh[so] = *(const uint4*)(Khb + r*128 + u*8);
                *(uint4*)&sKl[so] = *(const uint4*)(Klb + r*128 + u*8);
                *(uint4*)&sV[so]  = *(const uint4*)(Vb + (size_t)r*4096 + u*8);
            }
        }
        __syncthreads();

        float sacc[8][4];
#pragma unroll
        for (int j = 0; j < 8; j++)
#pragma unroll
            for (int r = 0; r < 4; r++) sacc[j][r] = 0.f;

        const int krow2 = ((lane >> 4) & 1)*8 + (lane & 7);
        const int kcol  = ((lane >> 3) & 1)*8;
#pragma unroll
        for (int ks = 0; ks < 8; ks++) {
            uint32_t aq[4];
            uint32_t aoff = (uint32_t)(((wr + (lane & 15))*QS + ks*16 + (lane >> 4)*8)*2);
            ldm_x4(aq, s2u(sQ) + aoff);
#pragma unroll
            for (int j2 = 0; j2 < 4; j2++) {
                uint32_t th[4], tl[4];
                uint32_t off = (uint32_t)(((j2*16 + krow2)*QS + ks*16 + kcol)*2);
                ldm_x4(th, s2u(sKh) + off);
                ldm_x4(tl, s2u(sKl) + off);
                mma_f16(sacc[2*j2],   aq, th);
                mma_f16(sacc[2*j2],   aq, tl);
                mma_f16(sacc[2*j2+1], aq, th + 2);
                mma_f16(sacc[2*j2+1], aq, tl + 2);
            }
        }

        if (kt == qt) {
            int r0 = wr + (lane >> 2);
#pragma unroll
            for (int j = 0; j < 8; j++) {
                int cbase = j*8 + (lane & 3)*2;
                if (cbase     > r0)     sacc[j][0] = -1e30f;
                if (cbase + 1 > r0)     sacc[j][1] = -1e30f;
                if (cbase     > r0 + 8) sacc[j][2] = -1e30f;
                if (cbase + 1 > r0 + 8) sacc[j][3] = -1e30f;
            }
        }

        float t0 = -1e30f, t1 = -1e30f;
#pragma unroll
        for (int j = 0; j < 8; j++) {
            t0 = fmaxf(t0, fmaxf(sacc[j][0], sacc[j][1]));
            t1 = fmaxf(t1, fmaxf(sacc[j][2], sacc[j][3]));
        }
        t0 = fmaxf(t0, __shfl_xor_sync(0xffffffffu, t0, 1));
        t0 = fmaxf(t0, __shfl_xor_sync(0xffffffffu, t0, 2));
        t1 = fmaxf(t1, __shfl_xor_sync(0xffffffffu, t1, 1));
        t1 = fmaxf(t1, __shfl_xor_sync(0xffffffffu, t1, 2));
        float nm0 = fmaxf(m0, t0), nm1 = fmaxf(m1, t1);
        float c0 = ex2(m0 - nm0), c1 = ex2(m1 - nm1);
        float rs0 = 0.f, rs1 = 0.f;
#pragma unroll
        for (int j = 0; j < 8; j++) {
            sacc[j][0] = ex2(sacc[j][0] - nm0);
            sacc[j][1] = ex2(sacc[j][1] - nm0);
            sacc[j][2] = ex2(sacc[j][2] - nm1);
            sacc[j][3] = ex2(sacc[j][3] - nm1);
            rs0 += sacc[j][0] + sacc[j][1];
            rs1 += sacc[j][2] + sacc[j][3];
        }
        rs0 += __shfl_xor_sync(0xffffffffu, rs0, 1);
        rs0 += __shfl_xor_sync(0xffffffffu, rs0, 2);
        rs1 += __shfl_xor_sync(0xffffffffu, rs1, 1);
        rs1 += __shfl_xor_sync(0xffffffffu, rs1, 2);
        ls0 = ls0*c0 + rs0; ls1 = ls1*c1 + rs1;
        m0 = nm0; m1 = nm1;
#pragma unroll
        for (int n = 0; n < 16; n++) {
            oacc[n][0] *= c0; oacc[n][1] *= c0;
            oacc[n][2] *= c1; oacc[n][3] *= c1;
        }

#pragma unroll
        for (int t = 0; t < 4; t++) {
            uint32_t ph[4];
            __half2 p0 = __floats2half2_rn(sacc[2*t][0],   sacc[2*t][1]);
            __half2 p1 = __floats2half2_rn(sacc[2*t][2],   sacc[2*t][3]);
            __half2 p2 = __floats2half2_rn(sacc[2*t+1][0], sacc[2*t+1][1]);
            __half2 p3 = __floats2half2_rn(sacc[2*t+1][2], sacc[2*t+1][3]);
            ph[0] = *(uint32_t*)&p0; ph[1] = *(uint32_t*)&p1;
            ph[2] = *(uint32_t*)&p2; ph[3] = *(uint32_t*)&p3;
            uint32_t vrow = (uint32_t)((t*16 + (lane & 15))*QS*2);
            uint32_t vcolsel = (uint32_t)(((lane >> 4) & 1)*8*2);
#pragma unroll
            for (int n2 = 0; n2 < 8; n2++) {
                uint32_t th[4];
                uint32_t off = vrow + (uint32_t)(n2*16*2) + vcolsel;
                ldm_x4t(th, s2u(sV) + off);
                mma_f16(oacc[2*n2],   ph, th);
                mma_f16(oacc[2*n2+1], ph, th + 2);
            }
        }
    }

    const int rloc = wr + (lane >> 2);
    if (qt < 16) {
        float inv0 = 1.f/ls0, inv1 = 1.f/ls1;
        int grow = qt*64 + rloc;
        __half* dst0 = X + (size_t)(b*LL + grow)*2048 + h*128;
        __half* dst1 = dst0 + (size_t)8*2048;
#pragma unroll
        for (int n = 0; n < 16; n++) {
            int col = n*8 + (lane & 3)*2;
            *(__half2*)(dst0 + col) = __floats2half2_rn(oacc[n][0]*inv0, oacc[n][1]*inv0);
            *(__half2*)(dst1 + col) = __floats2half2_rn(oacc[n][2]*inv1, oacc[n][3]*inv1);
        }
    } else {
        float* pob = po + ((size_t)((split*16 + (qt - 16))*16 + bh))*8192;
#pragma unroll
        for (int n = 0; n < 16; n++) {
            int col = n*8 + (lane & 3)*2;
            float2 v0 = {oacc[n][0], oacc[n][1]};
            float2 v1 = {oacc[n][2], oacc[n][3]};
            *(float2*)(pob + (size_t)rloc*128 + col) = v0;
            *(float2*)(pob + (size_t)(rloc + 8)*128 + col) = v1;
        }
        if ((lane & 3) == 0) {
            float* pmb = pml + ((split*16 + (qt - 16))*16 + bh)*128;
            pmb[rloc*2]       = m0; pmb[rloc*2 + 1]       = ls0;
            pmb[(rloc+8)*2]   = m1; pmb[(rloc+8)*2 + 1]   = ls1;
        }
    }
}

// ---------- split-KV merge ----------
__global__ void flash_merge(const float* __restrict__ po, const float* __restrict__ pml,
                            __half* __restrict__ X)
{
    __shared__ float sml[256];
    const int qq = blockIdx.x, bh = blockIdx.y;
    const int qt = 16 + qq;
    const int b = bh >> 3, h = bh & 7;
    const int tid = threadIdx.x;

    if (tid < 128) sml[tid] = pml[((0*16 + qq)*16 + bh)*128 + tid];
    else           sml[tid] = pml[((1*16 + qq)*16 + bh)*128 + tid - 128];
    __syncthreads();

    const float* po0 = po + ((size_t)((0*16 + qq)*16 + bh))*8192;
    const float* po1 = po + ((size_t)((1*16 + qq)*16 + bh))*8192;

#pragma unroll
    for (int t = 0; t < 8; t++) {
        int f = tid + t*256;
        int row = f >> 5, c4 = (f & 31)*4;
        float m0 = sml[row*2],       l0 = sml[row*2 + 1];
        float m1 = sml[128 + row*2], l1 = sml[128 + row*2 + 1];
        float m = fmaxf(m0, m1);
        float w0 = ex2(m0 - m), w1 = ex2(m1 - m);
        float inv = 1.f/(l0*w0 + l1*w1);
        float4 a = *(const float4*)(po0 + (size_t)row*128 + c4);
        float4 c = *(const float4*)(po1 + (size_t)row*128 + c4);
        float o0 = (a.x*w0 + c.x*w1)*inv;
        float o1 = (a.y*w0 + c.y*w1)*inv;
        float o2 = (a.z*w0 + c.z*w1)*inv;
        float o3 = (a.w*w0 + c.w*w1)*inv;
        int grow = qt*64 + row;
        __half* dst = X + (size_t)(b*LL + grow)*2048 + h*128 + c4;
        __half2 h0 = __floats2half2_rn(o0, o1);
        __half2 h1 = __floats2half2_rn(o2, o3);
        uint2 ov = {*(uint32_t*)&h0, *(uint32_t*)&h1};
        *(uint2*)dst = ov;
    }
}

// ---------- linear attn chunk summary via HMMA (fp16 K in, fp16 A out) ----------
extern __shared__ __align__(16) __half csmh[];
__global__ __launch_bounds__(256)
void lin_chunk_mma(const __half* __restrict__ klin, const __half* __restrict__ qkv,
                   const float* __restrict__ slope, __half* __restrict__ Aout)
{
    __half* sWK = csmh;
    __half* sV  = sWK + 128*QS;

    const int c = blockIdx.x, h = blockIdx.y, b = blockIdx.z;
    const float s = slope[h];
    const int tid = threadIdx.x, lane = tid & 31, wid = tid >> 5;
    const int kvl = h >> 1;
    const int m0w = wid*16;

    {
        const __half* Kb = klin + ((size_t)(b*4 + kvl)*LL + c*128)*128;
#pragma unroll
        for (int t = 0; t < 8; t++) {
            int idx = tid + t*256;
            int j = idx >> 4, u = idx & 15;
            float w = ex2(-LOG2E * s * (float)(127 - j));
            uint4 kv = *(const uint4*)(Kb + (size_t)j*128 + u*8);
            __half2* hp = (__half2*)&kv;
            __half2 r[4];
#pragma unroll
            for (int e = 0; e < 4; e++) {
                float2 f = __half22float2(hp[e]);
                r[e] = __floats2half2_rn(f.x*w, f.y*w);
            }
            *(uint4*)&sWK[j*QS + u*8] = *(uint4*)r;
        }
        const __half* Vb = qkv + (size_t)(b*LL + c*128)*4096 + 3072 + (4 + kvl)*128;
#pragma unroll
        for (int t = 0; t < 8; t++) {
            int idx = tid + t*256;
            int j = idx >> 4, u = idx & 15;
            *(uint4*)&sV[j*QS + u*8] = *(const uint4*)(Vb + (size_t)j*4096 + u*8);
        }
    }
    __syncthreads();

    float acc[16][4];
#pragma unroll
    for (int n = 0; n < 16; n++)
#pragma unroll
        for (int r = 0; r < 4; r++) acc[n][r] = 0.f;

#pragma unroll
    for (int kc = 0; kc < 8; kc++) {
        uint32_t a[4];
        int jrow = kc*16 + (lane & 7) + ((lane >> 4) & 1)*8;
        int mcol = m0w + ((lane >> 3) & 1)*8;
        ldm_x4t(a, s2u(sWK) + (uint32_t)((jrow*QS + mcol)*2));
        uint32_t vrow = (uint32_t)((kc*16 + (lane & 15))*QS*2);
        uint32_t vcolsel = (uint32_t)(((lane >> 4) & 1)*8*2);
#pragma unroll
        for (int n2 = 0; n2 < 8; n2++) {
            uint32_t th[4];
            uint32_t off = vrow + (uint32_t)(n2*16*2) + vcolsel;
            ldm_x4t(th, s2u(sV) + off);
            mma_f16(acc[2*n2],   a, th);
            mma_f16(acc[2*n2+1], a, th + 2);
        }
    }

    __half* Ab = Aout + ((size_t)(b*8 + h)*NC + c)*16384;
    int row0 = m0w + (lane >> 2);
#pragma unroll
    for (int n = 0; n < 16; n++) {
        int col = n*8 + (lane & 3)*2;
        *(__half2*)(Ab + (size_t)row0*128 + col)       = __floats2half2_rn(acc[n][0], acc[n][1]);
        *(__half2*)(Ab + (size_t)(row0 + 8)*128 + col) = __floats2half2_rn(acc[n][2], acc[n][3]);
    }
}

// ---------- scan (fp16 A/P, fp32 carry) ----------
__global__ void lin_scan_kernel(const __half* __restrict__ Ain, const float* __restrict__ slope,
                                __half* __restrict__ Pout)
{
    const int f = blockIdx.x*256 + threadIdx.x;
    const int h = blockIdx.y, b = blockIdx.z;
    const float lam = expf(-128.0f * slope[h]);
    const size_t base = (size_t)(b*8 + h)*NC*16384 + f;
    float p = 0.f;
#pragma unroll
    for (int c = 0; c < NC; c++) {
        size_t off = base + (size_t)c*16384;
        Pout[off] = __float2half_rn(p);
        p = p*lam + __half2float(Ain[off]);
    }
}

// ---------- linear attn output via HMMA (all fp16 operands, P single) ----------
extern __shared__ __align__(16) __half osmh[];
__global__ __launch_bounds__(256)
void lin_out_mma(const __half* __restrict__ qlin, const __half* __restrict__ klin,
                 const __half* __restrict__ qkv, const __half* __restrict__ Pbuf,
                 const float* __restrict__ slope, float* __restrict__ lout)
{
    __half* sQ = osmh;
    __half* sK = sQ + 128*QS;
    __half* sV = sK + 128*QS;
    __half* sP = sV + 128*QS;

    const int c = blockIdx.x, h = blockIdx.y, b = blockIdx.z;
    const float s = slope[h];
    const float sl2 = s * LOG2E;
    const int tid = threadIdx.x, lane = tid & 31, wid = tid >> 5;
    const int kvl = h >> 1;
    const int wr = wid*16;

    {
        const __half* Qb = qlin + ((size_t)(b*8 + h)*LL + c*128)*128;
        const __half* Kb = klin + ((size_t)(b*4 + kvl)*LL + c*128)*128;
        const __half* Pb = Pbuf + ((size_t)(b*8 + h)*NC + c)*16384;
        const __half* Vb = qkv + (size_t)(b*LL + c*128)*4096 + 3072 + (4 + kvl)*128;
#pragma unroll
        for (int t = 0; t < 8; t++) {
            int idx = tid + t*256;
            int j = idx >> 4, u = idx & 15;
            uint32_t so = (uint32_t)(j*QS + u*8);
            *(uint4*)&sQ[so] = *(const uint4*)(Qb + (size_t)j*128 + u*8);
            *(uint4*)&sK[so] = *(const uint4*)(Kb + (size_t)j*128 + u*8);
            *(uint4*)&sP[so] = *(const uint4*)(Pb + (size_t)j*128 + u*8);
            *(uint4*)&sV[so] = *(const uint4*)(Vb + (size_t)j*4096 + u*8);
        }
    }
    __syncthreads();

    float sacc[16][4];
#pragma unroll
    for (int j = 0; j < 16; j++)
#pragma unroll
        for (int r = 0; r < 4; r++) sacc[j][r] = 0.f;

    const int krow2 = ((lane >> 4) & 1)*8 + (lane & 7);
    const int kcol  = ((lane >> 3) & 1)*8;
#pragma unroll
    for (int ks = 0; ks < 8; ks++) {
        uint32_t aq[4];
        uint32_t aoff = (uint32_t)(((wr + (lane & 15))*QS + ks*16 + (lane >> 4)*8)*2);
        ldm_x4(aq, s2u(sQ) + aoff);
#pragma unroll
        for (int j2 = 0; j2 < 8; j2++) {
            uint32_t tk[4];
            uint32_t boff = (uint32_t)(((j2*16 + krow2)*QS + ks*16 + kcol)*2);
            ldm_x4(tk, s2u(sK) + boff);
            mma_f16(sacc[2*j2],   aq, tk);
            mma_f16(sacc[2*j2+1], aq, tk + 2);
        }
    }

    {
        int i0 = wr + (lane >> 2);
#pragma unroll
        for (int j = 0; j < 16; j++) {
            int cb = j*8 + (lane & 3)*2;
#pragma unroll
            for (int r = 0; r < 4; r++) {
                int ig = i0 + ((r >= 2) ? 8 : 0);
                int jg = cb + (r & 1);
                sacc[j][r] = (ig >= jg) ? sacc[j][r]*ex2(-sl2*(float)(ig - jg)) : 0.f;
            }
        }
    }

    float acc[16][4];
#pragma unroll
    for (int n = 0; n < 16; n++)
#pragma unroll
        for (int r = 0; r < 4; r++) acc[n][r] = 0.f;

    // state term: Q @ P (single fp16)
#pragma unroll
    for (int kc = 0; kc < 8; kc++) {
        uint32_t aq[4];
        uint32_t aoff = (uint32_t)(((wr + (lane & 15))*QS + kc*16 + (lane >> 4)*8)*2);
        ldm_x4(aq, s2u(sQ) + aoff);
        uint32_t prow = (uint32_t)((kc*16 + (lane & 15))*QS*2);
        uint32_t pcolsel = (uint32_t)(((lane >> 4) & 1)*8*2);
#pragma unroll
        for (int n2 = 0; n2 < 8; n2++) {
            uint32_t th[4];
            uint32_t off = prow + (uint32_t)(n2*16*2) + pcolsel;
            ldm_x4t(th, s2u(sP) + off);
            mma_f16(acc[2*n2],   aq, th);
            mma_f16(acc[2*n2+1], aq, th + 2);
        }
    }
    {
        int i0 = wr + (lane >> 2);
        float f0 = ex2(-sl2*(float)(i0 + 1));
        float f1 = ex2(-sl2*(float)(i0 + 9));
#pragma unroll
        for (int n = 0; n < 16; n++) {
            acc[n][0] *= f0; acc[n][1] *= f0;
            acc[n][2] *= f1; acc[n][3] *= f1;
        }
    }

    // intra-chunk: E @ V
#pragma unroll
    for (int kc = 0; kc < 8; kc++) {
        uint32_t ph[4];
        __half2 p0 = __floats2half2_rn(sacc[2*kc][0],   sacc[2*kc][1]);
        __half2 p1 = __floats2half2_rn(sacc[2*kc][2],   sacc[2*kc][3]);
        __half2 p2 = __floats2half2_rn(sacc[2*kc+1][0], sacc[2*kc+1][1]);
        __half2 p3 = __floats2half2_rn(sacc[2*kc+1][2], sacc[2*kc+1][3]);
        ph[0] = *(uint32_t*)&p0; ph[1] = *(uint32_t*)&p1;
        ph[2] = *(uint32_t*)&p2; ph[3] = *(uint32_t*)&p3;
        uint32_t vrow = (uint32_t)((kc*16 + (lane & 15))*QS*2);
        uint32_t vcolsel = (uint32_t)(((lane >> 4) & 1)*8*2);
#pragma unroll
        for (int n2 = 0; n2 < 8; n2++) {
            uint32_t th[4];
            uint32_t off = vrow + (uint32_t)(n2*16*2) + vcolsel;
            ldm_x4t(th, s2u(sV) + off);
            mma_f16(acc[2*n2],   ph, th);
            mma_f16(acc[2*n2+1], ph, th + 2);
        }
    }

    int row0 = c*128 + wr + (lane >> 2);
    float* dst0 = lout + (size_t)(b*LL + row0)*1024 + h*128;
    float* dst1 = dst0 + (size_t)8*1024;
#pragma unroll
    for (int n = 0; n < 16; n++) {
        int col = n*8 + (lane & 3)*2;
        float2 v0 = {acc[n][0], acc[n][1]};
        float2 v1 = {acc[n][2], acc[n][3]};
        *(float2*)(dst0 + col) = v0;
        *(float2*)(dst1 + col) = v1;
    }
}

// ---------- SimpleRMSNorm -> fp16 X ----------
__global__ void rmsnorm_kernel(const float* __restrict__ lin, __half* __restrict__ X)
{
    __shared__ float red[8];
    const int row = blockIdx.x, tid = threadIdx.x;
    const float* src = lin + (size_t)row*1024;
    float ss = 0.f;
    float vals[4];
    *(float4*)vals = *(const float4*)(src + tid*4);
#pragma unroll
    for (int i = 0; i < 4; i++) ss += vals[i]*vals[i];
#pragma unroll
    for (int off = 16; off >= 1; off >>= 1)
        ss += __shfl_xor_sync(0xffffffffu, ss, off);
    if ((tid & 31) == 0) red[tid >> 5] = ss;
    __syncthreads();
    float tot = 0.f;
#pragma unroll
    for (int i = 0; i < 8; i++) tot += red[i];
    float inv = rsqrtf(tot * (1.0f/1024.0f) + 1e-6f);
    __half* dst = X + (size_t)row*2048 + 1024 + tid*4;
    __half2 o0 = __floats2half2_rn(vals[0]*inv, vals[1]*inv);
    __half2 o1 = __floats2half2_rn(vals[2]*inv, vals[3]*inv);
    uint2 ov = {*(uint32_t*)&o0, *(uint32_t*)&o1};
    *(uint2*)dst = ov;
}

extern "C" void kernel_launch(void* const* d_in, const int* in_sizes, int n_in,
                              void* d_out, int out_size)
{
    const float* hs   = (const float*)d_in[0];
    const float* slope= (const float*)d_in[3];
    const int*   pos  = (const int*)d_in[4];
    const float* Wq   = (const float*)d_in[5];
    const float* bq   = (const float*)d_in[6];
    const float* Wk   = (const float*)d_in[7];
    const float* bk   = (const float*)d_in[8];
    const float* Wv   = (const float*)d_in[9];
    const float* bv   = (const float*)d_in[10];
    const float* Wo   = (const float*)d_in[11];
    const float* qcw  = (const float*)d_in[12];
    const float* qcb  = (const float*)d_in[13];
    const float* kcw  = (const float*)d_in[14];
    const float* kcb  = (const float*)d_in[15];
    float* out = (float*)d_out;

    float *lin, *bqkv, *po, *pml;
    cudaGetSymbolAddress((void**)&lin,  g_lin);
    cudaGetSymbolAddress((void**)&bqkv, g_bqkv);
    cudaGetSymbolAddress((void**)&po,   g_po);
    cudaGetSymbolAddress((void**)&pml,  g_pml);
    __half *hsh,*xh,*qkvh,*wqkv,*woh,*qh,*kh,*kl,*qlin,*klin,*A,*P;
    cudaGetSymbolAddress((void**)&hsh,  g_hsh);
    cudaGetSymbolAddress((void**)&xh,   g_xh);
    cudaGetSymbolAddress((void**)&qkvh, g_qkvh);
    cudaGetSymbolAddress((void**)&wqkv, g_wqkv);
    cudaGetSymbolAddress((void**)&woh,  g_woh);
    cudaGetSymbolAddress((void**)&qh,   g_qh);
    cudaGetSymbolAddress((void**)&kh,   g_kh);
    cudaGetSymbolAddress((void**)&kl,   g_kl);
    cudaGetSymbolAddress((void**)&qlin, g_qlin);
    cudaGetSymbolAddress((void**)&klin, g_klin);
    cudaGetSymbolAddress((void**)&A,    g_A);
    cudaGetSymbolAddress((void**)&P,    g_P);

    const int FLASH_SMEM = 4*64*QS*2;
    const int CHUNK_SMEM = 2*128*QS*2;
    const int LOUT_SMEM  = 4*128*QS*2;             // 139264
    const int GEMM_SMEM  = 3*30720;
    cudaFuncSetAttribute(flash_mma,     cudaFuncAttributeMaxDynamicSharedMemorySize, FLASH_SMEM);
    cudaFuncSetAttribute(lin_chunk_mma, cudaFuncAttributeMaxDynamicSharedMemorySize, CHUNK_SMEM);
    cudaFuncSetAttribute(lin_out_mma,   cudaFuncAttributeMaxDynamicSharedMemorySize, LOUT_SMEM);
    cudaFuncSetAttribute(gemm_mma<true>,  cudaFuncAttributeMaxDynamicSharedMemorySize, GEMM_SMEM);
    cudaFuncSetAttribute(gemm_mma<false>, cudaFuncAttributeMaxDynamicSharedMemorySize, GEMM_SMEM);

    // prep
    convert_h<<<MM*HH/1024, 256>>>(hs, hsh);
    transpose_h<<<dim3(64, 64), dim3(32, 8)>>>(Wq, wqkv,               2048, 2048);
    transpose_h<<<dim3(32, 64), dim3(32, 8)>>>(Wk, wqkv + 2048*2048,   2048, 1024);
    transpose_h<<<dim3(32, 64), dim3(32, 8)>>>(Wv, wqkv + 3072*2048,   2048, 1024);
    cudaMemcpyAsync(bqkv,        bq, 2048*sizeof(float), cudaMemcpyDeviceToDevice);
    cudaMemcpyAsync(bqkv + 2048, bk, 1024*sizeof(float), cudaMemcpyDeviceToDevice);
    cudaMemcpyAsync(bqkv + 3072, bv, 1024*sizeof(float), cudaMemcpyDeviceToDevice);
    transpose_h<<<dim3(64, 64), dim3(32, 8)>>>(Wo, woh, 2048, 2048);

    // fused QKV projection -> fp16
    gemm_mma<true><<<dim3(16, 32), 256, GEMM_SMEM>>>(hsh, wqkv, bqkv, qkvh, 4096, 2048);

    // elementwise preprocessing
    rotary_kernel<<<dim3(LL, BB), 128>>>(qkvh, pos, qh, kh, kl);
    conv_silu_kernel<<<dim3(LL, BB), 256>>>(qkvh, qcw, qcb, kcw, kcb, qlin, klin);

    // softmax half: split-KV flash + merge
    flash_mma<<<dim3(2, 32, 16), 128, FLASH_SMEM>>>(qh, kh, kl, qkvh, po, pml, xh);
    flash_merge<<<dim3(16, 16), 256>>>(po, pml, xh);

    // linear half (fp16 end-to-end)
    lin_chunk_mma<<<dim3(NC, 8, BB), 256, CHUNK_SMEM>>>(klin, qkvh, slope, A);
    lin_scan_kernel<<<dim3(64, 8, BB), 256>>>(A, slope, P);
    lin_out_mma<<<dim3(NC, 8, BB), 256, LOUT_SMEM>>>(qlin, klin, qkvh, P, slope, lin);
    rmsnorm_kernel<<<MM, 256>>>(lin, xh);

    // output projection -> fp32
    gemm_mma<false><<<dim3(8, 32), 256, GEMM_SMEM>>>(xh, woh, nullptr, out, 2048, 2048);
}

// round 17
// speedup vs baseline: 5.9015x; 1.0582x over previous
#include <cuda_runtime.h>
#include <cuda_bf16.h>
#include <cuda_fp16.h>
#include <math.h>
#include <stdint.h>

#define BB 2
#define LL 2048
#define HH 2048
#define MM (BB*LL)
#define NC 16

// fp32 scratch
__device__ float g_lin [BB*LL*1024];
__device__ float g_bqkv[4096];
__device__ float g_po  [2*16*16*8192];
__device__ float g_pml [2*16*16*128];
// fp16 scratch
__device__ __half g_hsh [MM*HH];
__device__ __half g_xh  [MM*HH];
__device__ __half g_qkvh[MM*4096];
__device__ __half g_wqkv[4096*2048];
__device__ __half g_woh [2048*2048];
__device__ __half g_qh  [BB*8*LL*128];
__device__ __half g_kh  [BB*4*LL*128];
__device__ __half g_qlin[BB*8*LL*128];
__device__ __half g_klin[BB*4*LL*128];
__device__ __half g_A   [BB*8*NC*16384];
__device__ __half g_P   [BB*8*NC*16384];

// ---------------- mma.sync helpers ----------------
__device__ __forceinline__ uint32_t s2u(const void* p) {
    return (uint32_t)__cvta_generic_to_shared(p);
}
__device__ __forceinline__ void ldm_x4(uint32_t* r, uint32_t addr) {
    asm volatile("ldmatrix.sync.aligned.m8n8.x4.shared.b16 {%0,%1,%2,%3}, [%4];"
                 : "=r"(r[0]), "=r"(r[1]), "=r"(r[2]), "=r"(r[3]) : "r"(addr));
}
__device__ __forceinline__ void ldm_x4t(uint32_t* r, uint32_t addr) {
    asm volatile("ldmatrix.sync.aligned.m8n8.x4.trans.shared.b16 {%0,%1,%2,%3}, [%4];"
                 : "=r"(r[0]), "=r"(r[1]), "=r"(r[2]), "=r"(r[3]) : "r"(addr));
}
__device__ __forceinline__ void mma_f16(float* c, const uint32_t* a, const uint32_t* b) {
    asm volatile("mma.sync.aligned.m16n8k16.row.col.f32.f16.f16.f32 "
                 "{%0,%1,%2,%3}, {%4,%5,%6,%7}, {%8,%9}, {%0,%1,%2,%3};"
                 : "+f"(c[0]), "+f"(c[1]), "+f"(c[2]), "+f"(c[3])
                 : "r"(a[0]), "r"(a[1]), "r"(a[2]), "r"(a[3]), "r"(b[0]), "r"(b[1]));
}
__device__ __forceinline__ void cp16(uint32_t dst, const void* src) {
    asm volatile("cp.async.cg.shared.global [%0], [%1], 16;"
                 :: "r"(dst), "l"(__cvta_generic_to_global(src)));
}
#define CP_COMMIT() asm volatile("cp.async.commit_group;" ::: "memory")
#define CP_WAIT1()  asm volatile("cp.async.wait_group 1;" ::: "memory")
#define CP_WAIT0()  asm volatile("cp.async.wait_group 0;" ::: "memory")
__device__ __forceinline__ float ex2(float x) {
    float y; asm("ex2.approx.ftz.f32 %0, %1;" : "=f"(y) : "f"(x)); return y;
}
#define LOG2E 1.4426950408889634f

// ---------------- convert kernels ----------------
__global__ void convert_h(const float* __restrict__ in, __half* __restrict__ hi)
{
    int i = (blockIdx.x*256 + threadIdx.x)*4;
    float4 v = *(const float4*)(in + i);
    __half h[4] = {__float2half_rn(v.x), __float2half_rn(v.y),
                   __float2half_rn(v.z), __float2half_rn(v.w)};
    *(uint2*)(hi + i) = *(uint2*)h;
}

__global__ void transpose_h(const float* __restrict__ W, __half* __restrict__ Th,
                            int Kd, int N)
{
    __shared__ float t[32][33];
    int n0 = blockIdx.x*32, k0 = blockIdx.y*32;
    int tx = threadIdx.x, ty = threadIdx.y;
#pragma unroll
    for (int i = 0; i < 4; i++)
        t[ty + 8*i][tx] = W[(size_t)(k0 + ty + 8*i)*N + n0 + tx];
    __syncthreads();
#pragma unroll
    for (int i = 0; i < 4; i++) {
        float v = t[tx][ty + 8*i];
        Th[(size_t)(n0 + ty + 8*i)*Kd + k0 + tx] = __float2half_rn(v);
    }
}

// ---------------- fp16 HMMA GEMM, templated output type ----------------
#define AOFF   0
#define BOFF   10240
extern __shared__ __align__(16) __half gsm2[];
template<bool HOUT>
__global__ __launch_bounds__(256, 1)
void gemm_mma(const __half* __restrict__ Ah, const __half* __restrict__ Bh,
              const float* __restrict__ bias, void* __restrict__ Cv, int N, int Kd)
{
    const int STG = 30720;
    const int tid = threadIdx.x, lane = tid & 31, wid = tid >> 5;
    const int n0 = blockIdx.x*256, m0 = blockIdx.y*128;
    const int wrow = (wid >> 2)*64, wcol = (wid & 3)*64;
    const uint32_t su = s2u(gsm2);

    float acc[4][8][4];
#pragma unroll
    for (int i = 0; i < 4; i++)
#pragma unroll
        for (int j = 0; j < 8; j++)
#pragma unroll
            for (int r = 0; r < 4; r++) acc[i][j][r] = 0.f;

    const int nch = Kd >> 5;

    auto load_stage = [&](int ci, int st) {
        const int k0 = ci << 5;
        const uint32_t sb = su + st*STG;
#pragma unroll
        for (int p = 0; p < 6; p++) {
            int idx = tid + p*256;
            int r = idx >> 2, seg = idx & 3;
            uint32_t doff; const __half* src;
            if (r < 128) { doff = AOFF + r*80 + seg*16;            src = Ah + (size_t)(m0 + r)*Kd + k0 + seg*8; }
            else         { int rb = r - 128; doff = BOFF + rb*80 + seg*16; src = Bh + (size_t)(n0 + rb)*Kd + k0 + seg*8; }
            cp16(sb + doff, src);
        }
    };

    load_stage(0, 0); CP_COMMIT();
    if (nch > 1) { load_stage(1, 1); CP_COMMIT(); }

    for (int i = 0; i < nch; i++) {
        if (i + 1 < nch) CP_WAIT1(); else CP_WAIT0();
        __syncthreads();
        if (i + 2 < nch) { load_stage(i + 2, (i + 2) % 3); CP_COMMIT(); }

        const uint32_t sA = su + (i % 3)*STG;
        const uint32_t sB = sA + BOFF;
        const int arow = wrow + (lane & 15);
        const int acol = (lane >> 4)*8;
        const int brow2 = wcol + ((lane >> 4) & 1)*8 + (lane & 7);
        const int bcol  = ((lane >> 3) & 1)*8;

#pragma unroll
        for (int ks = 0; ks < 2; ks++) {
            uint32_t ah[4][4], bh[8][2];
#pragma unroll
            for (int f = 0; f < 4; f++) {
                uint32_t off = (uint32_t)(((arow + 16*f)*40 + acol + ks*16)*2);
                ldm_x4(ah[f], sA + off);
            }
#pragma unroll
            for (int f2 = 0; f2 < 4; f2++) {
                uint32_t tmp[4];
                uint32_t off = (uint32_t)(((brow2 + 16*f2)*40 + bcol + ks*16)*2);
                ldm_x4(tmp, sB + off);
                bh[2*f2][0]   = tmp[0]; bh[2*f2][1]   = tmp[1];
                bh[2*f2+1][0] = tmp[2]; bh[2*f2+1][1] = tmp[3];
            }
#pragma unroll
            for (int fi = 0; fi < 4; fi++)
#pragma unroll
                for (int fj = 0; fj < 8; fj++)
                    mma_f16(acc[fi][fj], ah[fi], bh[fj]);
        }
    }

    const int g = lane >> 2, c = lane & 3;
#pragma unroll
    for (int fi = 0; fi < 4; fi++)
#pragma unroll
        for (int fj = 0; fj < 8; fj++) {
            int rr = m0 + wrow + 16*fi + g;
            int cc = n0 + wcol + 8*fj + 2*c;
            float b0 = bias ? bias[cc] : 0.f;
            float b1 = bias ? bias[cc + 1] : 0.f;
            float o00 = acc[fi][fj][0] + b0, o01 = acc[fi][fj][1] + b1;
            float o10 = acc[fi][fj][2] + b0, o11 = acc[fi][fj][3] + b1;
            if (HOUT) {
                __half* C = (__half*)Cv;
                *(__half2*)(C + (size_t)rr*N + cc)       = __floats2half2_rn(o00, o01);
                *(__half2*)(C + (size_t)(rr + 8)*N + cc) = __floats2half2_rn(o10, o11);
            } else {
                float* C = (float*)Cv;
                float2 v0 = {o00, o01}, v1 = {o10, o11};
                *(float2*)(C + (size_t)rr*N + cc) = v0;
                *(float2*)(C + (size_t)(rr + 8)*N + cc) = v1;
            }
        }
}

// ---------- rotary (K single fp16) ----------
__global__ void rotary_kernel(const __half* __restrict__ qkv,
                              const int* __restrict__ pos, __half* __restrict__ qh,
                              __half* __restrict__ kh)
{
    const int l = blockIdx.x, b = blockIdx.y, d = threadIdx.x;
    const float p = (float)pos[l];
    const int dm = d & 63;
    const float ang = p * powf(1.0e6f, -((float)(2*dm))/128.0f);
    const float cs = cosf(ang), sn = sinf(ang);
    const float qscale = 0.08838834764831845f * LOG2E;
    const __half* row = qkv + (size_t)(b*LL + l)*4096;
#pragma unroll
    for (int h = 0; h < 8; h++) {
        float x  = __half2float(row[h*128 + d]);
        float xr = (d < 64) ? -__half2float(row[h*128 + d + 64])
                            :  __half2float(row[h*128 + d - 64]);
        qh[((size_t)(b*8 + h)*LL + l)*128 + d] = __float2half_rn((x*cs + xr*sn)*qscale);
    }
#pragma unroll
    for (int khh = 0; khh < 4; khh++) {
        float x  = __half2float(row[2048 + khh*128 + d]);
        float xr = (d < 64) ? -__half2float(row[2048 + khh*128 + d + 64])
                            :  __half2float(row[2048 + khh*128 + d - 64]);
        kh[((size_t)(b*4 + khh)*LL + l)*128 + d] = __float2half_rn(x*cs + xr*sn);
    }
}

// ---------- causal depthwise conv(K=4) + SiLU -> fp16 outputs ----------
__global__ void conv_silu_kernel(const __half* __restrict__ qkv,
                                 const float* __restrict__ qcw, const float* __restrict__ qcb,
                                 const float* __restrict__ kcw, const float* __restrict__ kcb,
                                 __half* __restrict__ qlin, __half* __restrict__ klin)
{
    const int l = blockIdx.x, b = blockIdx.y, tid = threadIdx.x;
    for (int c = tid; c < 1024; c += 256) {
        float y = qcb[c];
#pragma unroll
        for (int i = 0; i < 4; i++) {
            int lp = l - 3 + i;
            if (lp >= 0) y += __half2float(qkv[(size_t)(b*LL + lp)*4096 + 1024 + c]) * qcw[c*4 + i];
        }
        y = y / (1.0f + expf(-y));
        qlin[((size_t)(b*8 + (c >> 7))*LL + l)*128 + (c & 127)] = __float2half_rn(y);
    }
    for (int c = 512 + tid; c < 1024; c += 256) {
        float y = kcb[c];
#pragma unroll
        for (int i = 0; i < 4; i++) {
            int lp = l - 3 + i;
            if (lp >= 0) y += __half2float(qkv[(size_t)(b*LL + lp)*4096 + 2048 + c]) * kcw[c*4 + i];
        }
        y = y / (1.0f + expf(-y));
        klin[((size_t)(b*4 + ((c - 512) >> 7))*LL + l)*128 + (c & 127)] = __float2half_rn(y);
    }
}

// ---------- flash attention, split-KV, K and V single fp16 ----------
#define QS 136
extern __shared__ __align__(16) __half fsmh[];
__global__ __launch_bounds__(128)
void flash_mma(const __half* __restrict__ qh, const __half* __restrict__ kh,
               const __half* __restrict__ qkv,
               float* __restrict__ po, float* __restrict__ pml, __half* __restrict__ X)
{
    const int qt = 31 - (int)blockIdx.y;
    const int split = blockIdx.x;
    if (split == 1 && qt < 16) return;
    const int bh = blockIdx.z;
    const int b = bh >> 3, h = bh & 7;

    __half* sQ = fsmh;
    __half* sK = sQ + 64*QS;
    __half* sV = sK + 64*QS;

    const int tid = threadIdx.x, lane = tid & 31, wid = tid >> 5;
    const int kvh = h >> 1;
    const int wr = wid*16;

    {
        const __half* Qb = qh + ((size_t)(b*8 + h)*LL + qt*64)*128;
#pragma unroll
        for (int t = 0; t < 8; t++) {
            int idx = tid + t*128;
            int r = idx >> 4, u = idx & 15;
            *(uint4*)&sQ[r*QS + u*8] = *(const uint4*)(Qb + r*128 + u*8);
        }
    }

    float m0 = -INFINITY, m1 = -INFINITY, ls0 = 0.f, ls1 = 0.f;
    float oacc[16][4];
#pragma unroll
    for (int n = 0; n < 16; n++)
#pragma unroll
        for (int r = 0; r < 4; r++) oacc[n][r] = 0.f;

    const __half* Khb0 = kh + (size_t)(b*4 + kvh)*LL*128;
    const __half* Vb0  = qkv + (size_t)(b*LL)*4096 + 3072 + kvh*128;

    const int kt0 = split*16;
    const int ktend = (qt < kt0 + 15) ? qt : (kt0 + 15);

    for (int kt = kt0; kt <= ktend; kt++) {
        __syncthreads();
        {
            const __half* Khb = Khb0 + (size_t)(kt*64)*128;
            const __half* Vb  = Vb0  + (size_t)(kt*64)*4096;
#pragma unroll
            for (int t = 0; t < 8; t++) {
                int idx = tid + t*128;
                int r = idx >> 4, u = idx & 15;
                uint32_t so = (uint32_t)(r*QS + u*8);
                *(uint4*)&sK[so] = *(const uint4*)(Khb + r*128 + u*8);
                *(uint4*)&sV[so] = *(const uint4*)(Vb + (size_t)r*4096 + u*8);
            }
        }
        __syncthreads();

        float sacc[8][4];
#pragma unroll
        for (int j = 0; j < 8; j++)
#pragma unroll
            for (int r = 0; r < 4; r++) sacc[j][r] = 0.f;

        const int krow2 = ((lane >> 4) & 1)*8 + (lane & 7);
        const int kcol  = ((lane >> 3) & 1)*8;
#pragma unroll
        for (int ks = 0; ks < 8; ks++) {
            uint32_t aq[4];
            uint32_t aoff = (uint32_t)(((wr + (lane & 15))*QS + ks*16 + (lane >> 4)*8)*2);
            ldm_x4(aq, s2u(sQ) + aoff);
#pragma unroll
            for (int j2 = 0; j2 < 4; j2++) {
                uint32_t th[4];
                uint32_t off = (uint32_t)(((j2*16 + krow2)*QS + ks*16 + kcol)*2);
                ldm_x4(th, s2u(sK) + off);
                mma_f16(sacc[2*j2],   aq, th);
                mma_f16(sacc[2*j2+1], aq, th + 2);
            }
        }

        if (kt == qt) {
            int r0 = wr + (lane >> 2);
#pragma unroll
            for (int j = 0; j < 8; j++) {
                int cbase = j*8 + (lane & 3)*2;
                if (cbase     > r0)     sacc[j][0] = -1e30f;
                if (cbase + 1 > r0)     sacc[j][1] = -1e30f;
                if (cbase     > r0 + 8) sacc[j][2] = -1e30f;
                if (cbase + 1 > r0 + 8) sacc[j][3] = -1e30f;
            }
        }

        float t0 = -1e30f, t1 = -1e30f;
#pragma unroll
        for (int j = 0; j < 8; j++) {
            t0 = fmaxf(t0, fmaxf(sacc[j][0], sacc[j][1]));
            t1 = fmaxf(t1, fmaxf(sacc[j][2], sacc[j][3]));
        }
        t0 = fmaxf(t0, __shfl_xor_sync(0xffffffffu, t0, 1));
        t0 = fmaxf(t0, __shfl_xor_sync(0xffffffffu, t0, 2));
        t1 = fmaxf(t1, __shfl_xor_sync(0xffffffffu, t1, 1));
        t1 = fmaxf(t1, __shfl_xor_sync(0xffffffffu, t1, 2));
        float nm0 = fmaxf(m0, t0), nm1 = fmaxf(m1, t1);
        float c0 = ex2(m0 - nm0), c1 = ex2(m1 - nm1);
        float rs0 = 0.f, rs1 = 0.f;
#pragma unroll
        for (int j = 0; j < 8; j++) {
            sacc[j][0] = ex2(sacc[j][0] - nm0);
            sacc[j][1] = ex2(sacc[j][1] - nm0);
            sacc[j][2] = ex2(sacc[j][2] - nm1);
            sacc[j][3] = ex2(sacc[j][3] - nm1);
            rs0 += sacc[j][0] + sacc[j][1];
            rs1 += sacc[j][2] + sacc[j][3];
        }
        rs0 += __shfl_xor_sync(0xffffffffu, rs0, 1);
        rs0 += __shfl_xor_sync(0xffffffffu, rs0, 2);
        rs1 += __shfl_xor_sync(0xffffffffu, rs1, 1);
        rs1 += __shfl_xor_sync(0xffffffffu, rs1, 2);
        ls0 = ls0*c0 + rs0; ls1 = ls1*c1 + rs1;
        m0 = nm0; m1 = nm1;
#pragma unroll
        for (int n = 0; n < 16; n++) {
            oacc[n][0] *= c0; oacc[n][1] *= c0;
            oacc[n][2] *= c1; oacc[n][3] *= c1;
        }

#pragma unroll
        for (int t = 0; t < 4; t++) {
            uint32_t ph[4];
            __half2 p0 = __floats2half2_rn(sacc[2*t][0],   sacc[2*t][1]);
            __half2 p1 = __floats2half2_rn(sacc[2*t][2],   sacc[2*t][3]);
            __half2 p2 = __floats2half2_rn(sacc[2*t+1][0], sacc[2*t+1][1]);
            __half2 p3 = __floats2half2_rn(sacc[2*t+1][2], sacc[2*t+1][3]);
            ph[0] = *(uint32_t*)&p0; ph[1] = *(uint32_t*)&p1;
            ph[2] = *(uint32_t*)&p2; ph[3] = *(uint32_t*)&p3;
            uint32_t vrow = (uint32_t)((t*16 + (lane & 15))*QS*2);
            uint32_t vcolsel = (uint32_t)(((lane >> 4) & 1)*8*2);
#pragma unroll
            for (int n2 = 0; n2 < 8; n2++) {
                uint32_t th[4];
                uint32_t off = vrow + (uint32_t)(n2*16*2) + vcolsel;
                ldm_x4t(th, s2u(sV) + off);
                mma_f16(oacc[2*n2],   ph, th);
                mma_f16(oacc[2*n2+1], ph, th + 2);
            }
        }
    }

    const int rloc = wr + (lane >> 2);
    if (qt < 16) {
        float inv0 = 1.f/ls0, inv1 = 1.f/ls1;
        int grow = qt*64 + rloc;
        __half* dst0 = X + (size_t)(b*LL + grow)*2048 + h*128;
        __half* dst1 = dst0 + (size_t)8*2048;
#pragma unroll
        for (int n = 0; n < 16; n++) {
            int col = n*8 + (lane & 3)*2;
            *(__half2*)(dst0 + col) = __floats2half2_rn(oacc[n][0]*inv0, oacc[n][1]*inv0);
            *(__half2*)(dst1 + col) = __floats2half2_rn(oacc[n][2]*inv1, oacc[n][3]*inv1);
        }
    } else {
        float* pob = po + ((size_t)((split*16 + (qt - 16))*16 + bh))*8192;
#pragma unroll
        for (int n = 0; n < 16; n++) {
            int col = n*8 + (lane & 3)*2;
            float2 v0 = {oacc[n][0], oacc[n][1]};
            float2 v1 = {oacc[n][2], oacc[n][3]};
            *(float2*)(pob + (size_t)rloc*128 + col) = v0;
            *(float2*)(pob + (size_t)(rloc + 8)*128 + col) = v1;
        }
        if ((lane & 3) == 0) {
            float* pmb = pml + ((split*16 + (qt - 16))*16 + bh)*128;
            pmb[rloc*2]       = m0; pmb[rloc*2 + 1]       = ls0;
            pmb[(rloc+8)*2]   = m1; pmb[(rloc+8)*2 + 1]   = ls1;
        }
    }
}

// ---------- split-KV merge ----------
__global__ void flash_merge(const float* __restrict__ po, const float* __restrict__ pml,
                            __half* __restrict__ X)
{
    __shared__ float sml[256];
    const int qq = blockIdx.x, bh = blockIdx.y;
    const int qt = 16 + qq;
    const int b = bh >> 3, h = bh & 7;
    const int tid = threadIdx.x;

    if (tid < 128) sml[tid] = pml[((0*16 + qq)*16 + bh)*128 + tid];
    else           sml[tid] = pml[((1*16 + qq)*16 + bh)*128 + tid - 128];
    __syncthreads();

    const float* po0 = po + ((size_t)((0*16 + qq)*16 + bh))*8192;
    const float* po1 = po + ((size_t)((1*16 + qq)*16 + bh))*8192;

#pragma unroll
    for (int t = 0; t < 8; t++) {
        int f = tid + t*256;
        int row = f >> 5, c4 = (f & 31)*4;
        float m0 = sml[row*2],       l0 = sml[row*2 + 1];
        float m1 = sml[128 + row*2], l1 = sml[128 + row*2 + 1];
        float m = fmaxf(m0, m1);
        float w0 = ex2(m0 - m), w1 = ex2(m1 - m);
        float inv = 1.f/(l0*w0 + l1*w1);
        float4 a = *(const float4*)(po0 + (size_t)row*128 + c4);
        float4 c = *(const float4*)(po1 + (size_t)row*128 + c4);
        float o0 = (a.x*w0 + c.x*w1)*inv;
        float o1 = (a.y*w0 + c.y*w1)*inv;
        float o2 = (a.z*w0 + c.z*w1)*inv;
        float o3 = (a.w*w0 + c.w*w1)*inv;
        int grow = qt*64 + row;
        __half* dst = X + (size_t)(b*LL + grow)*2048 + h*128 + c4;
        __half2 h0 = __floats2half2_rn(o0, o1);
        __half2 h1 = __floats2half2_rn(o2, o3);
        uint2 ov = {*(uint32_t*)&h0, *(uint32_t*)&h1};
        *(uint2*)dst = ov;
    }
}

// ---------- linear attn chunk summary via HMMA ----------
extern __shared__ __align__(16) __half csmh[];
__global__ __launch_bounds__(256)
void lin_chunk_mma(const __half* __restrict__ klin, const __half* __restrict__ qkv,
                   const float* __restrict__ slope, __half* __restrict__ Aout)
{
    __half* sWK = csmh;
    __half* sV  = sWK + 128*QS;

    const int c = blockIdx.x, h = blockIdx.y, b = blockIdx.z;
    const float s = slope[h];
    const int tid = threadIdx.x, lane = tid & 31, wid = tid >> 5;
    const int kvl = h >> 1;
    const int m0w = wid*16;

    {
        const __half* Kb = klin + ((size_t)(b*4 + kvl)*LL + c*128)*128;
#pragma unroll
        for (int t = 0; t < 8; t++) {
            int idx = tid + t*256;
            int j = idx >> 4, u = idx & 15;
            float w = ex2(-LOG2E * s * (float)(127 - j));
            uint4 kv = *(const uint4*)(Kb + (size_t)j*128 + u*8);
            __half2* hp = (__half2*)&kv;
            __half2 r[4];
#pragma unroll
            for (int e = 0; e < 4; e++) {
                float2 f = __half22float2(hp[e]);
                r[e] = __floats2half2_rn(f.x*w, f.y*w);
            }
            *(uint4*)&sWK[j*QS + u*8] = *(uint4*)r;
        }
        const __half* Vb = qkv + (size_t)(b*LL + c*128)*4096 + 3072 + (4 + kvl)*128;
#pragma unroll
        for (int t = 0; t < 8; t++) {
            int idx = tid + t*256;
            int j = idx >> 4, u = idx & 15;
            *(uint4*)&sV[j*QS + u*8] = *(const uint4*)(Vb + (size_t)j*4096 + u*8);
        }
    }
    __syncthreads();

    float acc[16][4];
#pragma unroll
    for (int n = 0; n < 16; n++)
#pragma unroll
        for (int r = 0; r < 4; r++) acc[n][r] = 0.f;

#pragma unroll
    for (int kc = 0; kc < 8; kc++) {
        uint32_t a[4];
        int jrow = kc*16 + (lane & 7) + ((lane >> 4) & 1)*8;
        int mcol = m0w + ((lane >> 3) & 1)*8;
        ldm_x4t(a, s2u(sWK) + (uint32_t)((jrow*QS + mcol)*2));
        uint32_t vrow = (uint32_t)((kc*16 + (lane & 15))*QS*2);
        uint32_t vcolsel = (uint32_t)(((lane >> 4) & 1)*8*2);
#pragma unroll
        for (int n2 = 0; n2 < 8; n2++) {
            uint32_t th[4];
            uint32_t off = vrow + (uint32_t)(n2*16*2) + vcolsel;
            ldm_x4t(th, s2u(sV) + off);
            mma_f16(acc[2*n2],   a, th);
            mma_f16(acc[2*n2+1], a, th + 2);
        }
    }

    __half* Ab = Aout + ((size_t)(b*8 + h)*NC + c)*16384;
    int row0 = m0w + (lane >> 2);
#pragma unroll
    for (int n = 0; n < 16; n++) {
        int col = n*8 + (lane & 3)*2;
        *(__half2*)(Ab + (size_t)row0*128 + col)       = __floats2half2_rn(acc[n][0], acc[n][1]);
        *(__half2*)(Ab + (size_t)(row0 + 8)*128 + col) = __floats2half2_rn(acc[n][2], acc[n][3]);
    }
}

// ---------- scan (fp16 A/P, fp32 carry) ----------
__global__ void lin_scan_kernel(const __half* __restrict__ Ain, const float* __restrict__ slope,
                                __half* __restrict__ Pout)
{
    const int f = blockIdx.x*256 + threadIdx.x;
    const int h = blockIdx.y, b = blockIdx.z;
    const float lam = expf(-128.0f * slope[h]);
    const size_t base = (size_t)(b*8 + h)*NC*16384 + f;
    float p = 0.f;
#pragma unroll
    for (int c = 0; c < NC; c++) {
        size_t off = base + (size_t)c*16384;
        Pout[off] = __float2half_rn(p);
        p = p*lam + __half2float(Ain[off]);
    }
}

// ---------- linear attn output via HMMA ----------
extern __shared__ __align__(16) __half osmh[];
__global__ __launch_bounds__(256)
void lin_out_mma(const __half* __restrict__ qlin, const __half* __restrict__ klin,
                 const __half* __restrict__ qkv, const __half* __restrict__ Pbuf,
                 const float* __restrict__ slope, float* __restrict__ lout)
{
    __half* sQ = osmh;
    __half* sK = sQ + 128*QS;
    __half* sV = sK + 128*QS;
    __half* sP = sV + 128*QS;

    const int c = blockIdx.x, h = blockIdx.y, b = blockIdx.z;
    const float s = slope[h];
    const float sl2 = s * LOG2E;
    const int tid = threadIdx.x, lane = tid & 31, wid = tid >> 5;
    const int kvl = h >> 1;
    const int wr = wid*16;

    {
        const __half* Qb = qlin + ((size_t)(b*8 + h)*LL + c*128)*128;
        const __half* Kb = klin + ((size_t)(b*4 + kvl)*LL + c*128)*128;
        const __half* Pb = Pbuf + ((size_t)(b*8 + h)*NC + c)*16384;
        const __half* Vb = qkv + (size_t)(b*LL + c*128)*4096 + 3072 + (4 + kvl)*128;
#pragma unroll
        for (int t = 0; t < 8; t++) {
            int idx = tid + t*256;
            int j = idx >> 4, u = idx & 15;
            uint32_t so = (uint32_t)(j*QS + u*8);
            *(uint4*)&sQ[so] = *(const uint4*)(Qb + (size_t)j*128 + u*8);
            *(uint4*)&sK[so] = *(const uint4*)(Kb + (size_t)j*128 + u*8);
            *(uint4*)&sP[so] = *(const uint4*)(Pb + (size_t)j*128 + u*8);
            *(uint4*)&sV[so] = *(const uint4*)(Vb + (size_t)j*4096 + u*8);
        }
    }
    __syncthreads();

    float sacc[16][4];
#pragma unroll
    for (int j = 0; j < 16; j++)
#pragma unroll
        for (int r = 0; r < 4; r++) sacc[j][r] = 0.f;

    const int krow2 = ((lane >> 4) & 1)*8 + (lane & 7);
    const int kcol  = ((lane >> 3) & 1)*8;
#pragma unroll
    for (int ks = 0; ks < 8; ks++) {
        uint32_t aq[4];
        uint32_t aoff = (uint32_t)(((wr + (lane & 15))*QS + ks*16 + (lane >> 4)*8)*2);
        ldm_x4(aq, s2u(sQ) + aoff);
#pragma unroll
        for (int j2 = 0; j2 < 8; j2++) {
            uint32_t tk[4];
            uint32_t boff = (uint32_t)(((j2*16 + krow2)*QS + ks*16 + kcol)*2);
            ldm_x4(tk, s2u(sK) + boff);
            mma_f16(sacc[2*j2],   aq, tk);
            mma_f16(sacc[2*j2+1], aq, tk + 2);
        }
    }

    {
        int i0 = wr + (lane >> 2);
#pragma unroll
        for (int j = 0; j < 16; j++) {
            int cb = j*8 + (lane & 3)*2;
#pragma unroll
            for (int r = 0; r < 4; r++) {
                int ig = i0 + ((r >= 2) ? 8 : 0);
                int jg = cb + (r & 1);
                sacc[j][r] = (ig >= jg) ? sacc[j][r]*ex2(-sl2*(float)(ig - jg)) : 0.f;
            }
        }
    }

    float acc[16][4];
#pragma unroll
    for (int n = 0; n < 16; n++)
#pragma unroll
        for (int r = 0; r < 4; r++) acc[n][r] = 0.f;

#pragma unroll
    for (int kc = 0; kc < 8; kc++) {
        uint32_t aq[4];
        uint32_t aoff = (uint32_t)(((wr + (lane & 15))*QS + kc*16 + (lane >> 4)*8)*2);
        ldm_x4(aq, s2u(sQ) + aoff);
        uint32_t prow = (uint32_t)((kc*16 + (lane & 15))*QS*2);
        uint32_t pcolsel = (uint32_t)(((lane >> 4) & 1)*8*2);
#pragma unroll
        for (int n2 = 0; n2 < 8; n2++) {
            uint32_t th[4];
            uint32_t off = prow + (uint32_t)(n2*16*2) + pcolsel;
            ldm_x4t(th, s2u(sP) + off);
            mma_f16(acc[2*n2],   aq, th);
            mma_f16(acc[2*n2+1], aq, th + 2);
        }
    }
    {
        int i0 = wr + (lane >> 2);
        float f0 = ex2(-sl2*(float)(i0 + 1));
        float f1 = ex2(-sl2*(float)(i0 + 9));
#pragma unroll
        for (int n = 0; n < 16; n++) {
            acc[n][0] *= f0; acc[n][1] *= f0;
            acc[n][2] *= f1; acc[n][3] *= f1;
        }
    }

#pragma unroll
    for (int kc = 0; kc < 8; kc++) {
        uint32_t ph[4];
        __half2 p0 = __floats2half2_rn(sacc[2*kc][0],   sacc[2*kc][1]);
        __half2 p1 = __floats2half2_rn(sacc[2*kc][2],   sacc[2*kc][3]);
        __half2 p2 = __floats2half2_rn(sacc[2*kc+1][0], sacc[2*kc+1][1]);
        __half2 p3 = __floats2half2_rn(sacc[2*kc+1][2], sacc[2*kc+1][3]);
        ph[0] = *(uint32_t*)&p0; ph[1] = *(uint32_t*)&p1;
        ph[2] = *(uint32_t*)&p2; ph[3] = *(uint32_t*)&p3;
        uint32_t vrow = (uint32_t)((kc*16 + (lane & 15))*QS*2);
        uint32_t vcolsel = (uint32_t)(((lane >> 4) & 1)*8*2);
#pragma unroll
        for (int n2 = 0; n2 < 8; n2++) {
            uint32_t th[4];
            uint32_t off = vrow + (uint32_t)(n2*16*2) + vcolsel;
            ldm_x4t(th, s2u(sV) + off);
            mma_f16(acc[2*n2],   ph, th);
            mma_f16(acc[2*n2+1], ph, th + 2);
        }
    }

    int row0 = c*128 + wr + (lane >> 2);
    float* dst0 = lout + (size_t)(b*LL + row0)*1024 + h*128;
    float* dst1 = dst0 + (size_t)8*1024;
#pragma unroll
    for (int n = 0; n < 16; n++) {
        int col = n*8 + (lane & 3)*2;
        float2 v0 = {acc[n][0], acc[n][1]};
        float2 v1 = {acc[n][2], acc[n][3]};
        *(float2*)(dst0 + col) = v0;
        *(float2*)(dst1 + col) = v1;
    }
}

// ---------- SimpleRMSNorm -> fp16 X ----------
__global__ void rmsnorm_kernel(const float* __restrict__ lin, __half* __restrict__ X)
{
    __shared__ float red[8];
    const int row = blockIdx.x, tid = threadIdx.x;
    const float* src = lin + (size_t)row*1024;
    float ss = 0.f;
    float vals[4];
    *(float4*)vals = *(const float4*)(src + tid*4);
#pragma unroll
    for (int i = 0; i < 4; i++) ss += vals[i]*vals[i];
#pragma unroll
    for (int off = 16; off >= 1; off >>= 1)
        ss += __shfl_xor_sync(0xffffffffu, ss, off);
    if ((tid & 31) == 0) red[tid >> 5] = ss;
    __syncthreads();
    float tot = 0.f;
#pragma unroll
    for (int i = 0; i < 8; i++) tot += red[i];
    float inv = rsqrtf(tot * (1.0f/1024.0f) + 1e-6f);
    __half* dst = X + (size_t)row*2048 + 1024 + tid*4;
    __half2 o0 = __floats2half2_rn(vals[0]*inv, vals[1]*inv);
    __half2 o1 = __floats2half2_rn(vals[2]*inv, vals[3]*inv);
    uint2 ov = {*(uint32_t*)&o0, *(uint32_t*)&o1};
    *(uint2*)dst = ov;
}

extern "C" void kernel_launch(void* const* d_in, const int* in_sizes, int n_in,
                              void* d_out, int out_size)
{
    const float* hs   = (const float*)d_in[0];
    const float* slope= (const float*)d_in[3];
    const int*   pos  = (const int*)d_in[4];
    const float* Wq   = (const float*)d_in[5];
    const float* bq   = (const float*)d_in[6];
    const float* Wk   = (const float*)d_in[7];
    const float* bk   = (const float*)d_in[8];
    const float* Wv   = (const float*)d_in[9];
    const float* bv   = (const float*)d_in[10];
    const float* Wo   = (const float*)d_in[11];
    const float* qcw  = (const float*)d_in[12];
    const float* qcb  = (const float*)d_in[13];
    const float* kcw  = (const float*)d_in[14];
    const float* kcb  = (const float*)d_in[15];
    float* out = (float*)d_out;

    float *lin, *bqkv, *po, *pml;
    cudaGetSymbolAddress((void**)&lin,  g_lin);
    cudaGetSymbolAddress((void**)&bqkv, g_bqkv);
    cudaGetSymbolAddress((void**)&po,   g_po);
    cudaGetSymbolAddress((void**)&pml,  g_pml);
    __half *hsh,*xh,*qkvh,*wqkv,*woh,*qh,*kh,*qlin,*klin,*A,*P;
    cudaGetSymbolAddress((void**)&hsh,  g_hsh);
    cudaGetSymbolAddress((void**)&xh,   g_xh);
    cudaGetSymbolAddress((void**)&qkvh, g_qkvh);
    cudaGetSymbolAddress((void**)&wqkv, g_wqkv);
    cudaGetSymbolAddress((void**)&woh,  g_woh);
    cudaGetSymbolAddress((void**)&qh,   g_qh);
    cudaGetSymbolAddress((void**)&kh,   g_kh);
    cudaGetSymbolAddress((void**)&qlin, g_qlin);
    cudaGetSymbolAddress((void**)&klin, g_klin);
    cudaGetSymbolAddress((void**)&A,    g_A);
    cudaGetSymbolAddress((void**)&P,    g_P);

    const int FLASH_SMEM = 3*64*QS*2;              // 52224
    const int CHUNK_SMEM = 2*128*QS*2;
    const int LOUT_SMEM  = 4*128*QS*2;
    const int GEMM_SMEM  = 3*30720;
    cudaFuncSetAttribute(flash_mma,     cudaFuncAttributeMaxDynamicSharedMemorySize, FLASH_SMEM);
    cudaFuncSetAttribute(lin_chunk_mma, cudaFuncAttributeMaxDynamicSharedMemorySize, CHUNK_SMEM);
    cudaFuncSetAttribute(lin_out_mma,   cudaFuncAttributeMaxDynamicSharedMemorySize, LOUT_SMEM);
    cudaFuncSetAttribute(gemm_mma<true>,  cudaFuncAttributeMaxDynamicSharedMemorySize, GEMM_SMEM);
    cudaFuncSetAttribute(gemm_mma<false>, cudaFuncAttributeMaxDynamicSharedMemorySize, GEMM_SMEM);

    // prep
    convert_h<<<MM*HH/1024, 256>>>(hs, hsh);
    transpose_h<<<dim3(64, 64), dim3(32, 8)>>>(Wq, wqkv,               2048, 2048);
    transpose_h<<<dim3(32, 64), dim3(32, 8)>>>(Wk, wqkv + 2048*2048,   2048, 1024);
    transpose_h<<<dim3(32, 64), dim3(32, 8)>>>(Wv, wqkv + 3072*2048,   2048, 1024);
    cudaMemcpyAsync(bqkv,        bq, 2048*sizeof(float), cudaMemcpyDeviceToDevice);
    cudaMemcpyAsync(bqkv + 2048, bk, 1024*sizeof(float), cudaMemcpyDeviceToDevice);
    cudaMemcpyAsync(bqkv + 3072, bv, 1024*sizeof(float), cudaMemcpyDeviceToDevice);
    transpose_h<<<dim3(64, 64), dim3(32, 8)>>>(Wo, woh, 2048, 2048);

    // fused QKV projection -> fp16
    gemm_mma<true><<<dim3(16, 32), 256, GEMM_SMEM>>>(hsh, wqkv, bqkv, qkvh, 4096, 2048);

    // elementwise preprocessing
    rotary_kernel<<<dim3(LL, BB), 128>>>(qkvh, pos, qh, kh);
    conv_silu_kernel<<<dim3(LL, BB), 256>>>(qkvh, qcw, qcb, kcw, kcb, qlin, klin);

    // softmax half: split-KV flash + merge
    flash_mma<<<dim3(2, 32, 16), 128, FLASH_SMEM>>>(qh, kh, qkvh, po, pml, xh);
    flash_merge<<<dim3(16, 16), 256>>>(po, pml, xh);

    // linear half
    lin_chunk_mma<<<dim3(NC, 8, BB), 256, CHUNK_SMEM>>>(klin, qkvh, slope, A);
    lin_scan_kernel<<<dim3(64, 8, BB), 256>>>(A, slope, P);
    lin_out_mma<<<dim3(NC, 8, BB), 256, LOUT_SMEM>>>(qlin, klin, qkvh, P, slope, lin);
    rmsnorm_kernel<<<MM, 256>>>(lin, xh);

    // output projection -> fp32
    gemm_mma<false><<<dim3(8, 32), 256, GEMM_SMEM>>>(xh, woh, nullptr, out, 2048, 2048);
}